// round 13
// baseline (speedup 1.0000x reference)
#include <cuda_runtime.h>
#include <math_constants.h>

// Exact kNN graph: z-sorted dense scan with warp-uniform block skipping.
// PyG knn_graph(loop=False): B=16 x n=4096, D=3, k=16.
// Output (float32 flat): [nbr_global | centers | topk_d2], each total_n*K.

#define K     16
#define KP1   17
#define NPER  4096
#define TPB   256
#define CPG   (NPER / TPB)
#define NG    16
#define NB    256               // z bins
#define NBLK  (NPER / 8)        // 512 candidate blocks of 8
#define ZLO   (-4.5f)
#define HB    (9.0f / 256.0f)
#define INVHB (256.0f / 9.0f)

#define PB      12
#define SLOT_B  (TPB * 8u)
#define FLUSH_B (5u * SLOT_B)
#define INIT_KEY 0xFFFFFFFFFFFFFFFFull

// smem byte offsets (query kernel)
#define SM_SX    0
#define SM_SY    16384
#define SM_SZ    32768
#define SM_SS    49152
#define SM_SIDX  65536                 // u16[4096]      8192
#define SM_PEND  73728                 // u64[PB][256]  24576
#define SM_ZBMIN 98304                 // f32[512]       2048
#define SM_ZBMAX 100352                // f32[512]       2048
#define SM_TOTAL 102400                // 100 KB -> 2 CTAs/SM

__device__ float          g_sx  [NG][NPER];
__device__ float          g_sy  [NG][NPER];
__device__ float          g_sz  [NG][NPER];
__device__ float          g_ss  [NG][NPER];
__device__ unsigned short g_sidx[NG][NPER];   // sorted slot -> original idx

__device__ __forceinline__ int zbin(float z) {
    int b = (int)floorf((z - ZLO) * INVHB);
    return min(NB - 1, max(0, b));
}

#define FMA_F32X2(out, a, b, c) \
    asm("fma.rn.f32x2 %0, %1, %2, %3;" : "=l"(out) : "l"(a), "l"(b), "l"(c))
#define MUL_F32X2_(out, a, b) \
    asm("mul.rn.f32x2 %0, %1, %2;" : "=l"(out) : "l"(a), "l"(b))
#define ADD_F32X2_(out, a, b) \
    asm("add.rn.f32x2 %0, %1, %2;" : "=l"(out) : "l"(a), "l"(b))
#define PACK2(out, lo, hi) \
    asm("mov.b64 %0, {%1, %2};" : "=l"(out) : "r"(lo), "r"(hi))
#define UNPACK2(lo, hi, in) \
    asm("mov.b64 {%0, %1}, %2;" : "=r"(lo), "=r"(hi) : "l"(in))

// Branchless predicated push (R6-validated).
#define PUSHB(dv, jv)                                                         \
    do {                                                                      \
        unsigned long long kk_;                                               \
        asm("mov.b64 %0, {%1, %2};"                                           \
            : "=l"(kk_) : "r"((unsigned)(jv)), "r"(__float_as_uint(dv)));     \
        unsigned inc_;                                                        \
        asm volatile(                                                         \
            "{\n\t.reg .pred p;\n\t"                                          \
            "setp.le.f32 p, %1, %2;\n\t"                                      \
            "selp.u32 %0, %3, 0, p;\n\t"                                      \
            "@p st.shared.b64 [%4], %5;\n\t}"                                 \
            : "=r"(inc_)                                                      \
            : "f"(dv), "f"(worstf), "n"(SLOT_B),                              \
              "r"(pbase + offb), "l"(kk_)                                     \
            : "memory");                                                      \
        offb += inc_;                                                         \
    } while (0)

// Drain FIFO into the sorted K+1 u64-key list; key = (monotone dist bits,
// ORIGINAL idx) = jax.lax.top_k's exact (value, lower-index) order
// (validated R7/R11/R12). worstf only ever shrinks.
#define DRAIN()                                                               \
    {                                                                         \
        const int cnt_ = (int)(offb >> 11);                                   \
        offb = 0;                                                             \
        const unsigned long long* myp_ = pend + tid;                          \
        _Pragma("unroll 1")                                                   \
        for (int p_ = 0; p_ < cnt_; ++p_) {                                   \
            const unsigned long long kk_ = myp_[(size_t)p_ * TPB];            \
            unsigned lo_, hi_;                                                \
            UNPACK2(lo_, hi_, kk_);                                           \
            hi_ ^= ((unsigned)(((int)hi_) >> 31)) | 0x80000000u;              \
            unsigned long long key_ =                                         \
                ((unsigned long long)hi_ << 32) | (unsigned)sidx[lo_];        \
            if (key_ < bk[KP1 - 1]) {                                         \
                _Pragma("unroll")                                             \
                for (int m_ = 0; m_ < KP1; ++m_) {                            \
                    const bool sw_ = key_ < bk[m_];                           \
                    const unsigned long long l2_ = sw_ ? key_ : bk[m_];       \
                    key_   = sw_ ? bk[m_] : key_;                             \
                    bk[m_] = l2_;                                             \
                }                                                             \
            }                                                                 \
        }                                                                     \
        const unsigned wh_ = (unsigned)(bk[KP1 - 1] >> 32);                   \
        const unsigned wu_ = (wh_ & 0x80000000u) ? (wh_ ^ 0x80000000u) : ~wh_;\
        worstf = fminf(__uint_as_float(wu_), worstf);                         \
    }

// Warp z-window from each lane's current worst: radius slightly inflated so
// skipped blocks are strictly d > worst (ties at worst are never skipped).
#define REDUCE_BOUNDS()                                                       \
    {                                                                         \
        const float rad_ = __fsqrt_rn(worstf) * 1.0001f + 1e-6f;              \
        float lo_ = qz - rad_, hi_ = qz + rad_;                               \
        _Pragma("unroll")                                                     \
        for (int o_ = 16; o_ > 0; o_ >>= 1) {                                 \
            lo_ = fminf(lo_, __shfl_xor_sync(0xFFFFFFFFu, lo_, o_));          \
            hi_ = fmaxf(hi_, __shfl_xor_sync(0xFFFFFFFFu, hi_, o_));          \
        }                                                                     \
        zlo_w = lo_; zhi_w = hi_;                                             \
    }

// R6 dense 8-wide scan of block b_ (slots 8b_..8b_+7) + flush vote.
#define SCAN_BLOCK(b_)                                                        \
    {                                                                         \
        const int j0 = (b_) * 8;                                              \
        const ulonglong2 Xa = *(const ulonglong2*)(sx + j0);                  \
        const ulonglong2 Ya = *(const ulonglong2*)(sy + j0);                  \
        const ulonglong2 Za = *(const ulonglong2*)(sz + j0);                  \
        const ulonglong2 Sa = *(const ulonglong2*)(ss + j0);                  \
        const ulonglong2 Xb = *(const ulonglong2*)(sx + j0 + 4);              \
        const ulonglong2 Yb = *(const ulonglong2*)(sy + j0 + 4);              \
        const ulonglong2 Zb = *(const ulonglong2*)(sz + j0 + 4);              \
        const ulonglong2 Sb = *(const ulonglong2*)(ss + j0 + 4);              \
        unsigned long long dt, tt, dp0, dp1, dp2, dp3;                        \
        MUL_F32X2_(dt, qx2, Xa.x); FMA_F32X2(dt, qy2, Ya.x, dt);              \
        FMA_F32X2(dt, qz2, Za.x, dt);                                         \
        ADD_F32X2_(tt, Sa.x, qs2); FMA_F32X2(dp0, m2, dt, tt);                \
        MUL_F32X2_(dt, qx2, Xa.y); FMA_F32X2(dt, qy2, Ya.y, dt);              \
        FMA_F32X2(dt, qz2, Za.y, dt);                                         \
        ADD_F32X2_(tt, Sa.y, qs2); FMA_F32X2(dp1, m2, dt, tt);                \
        MUL_F32X2_(dt, qx2, Xb.x); FMA_F32X2(dt, qy2, Yb.x, dt);              \
        FMA_F32X2(dt, qz2, Zb.x, dt);                                         \
        ADD_F32X2_(tt, Sb.x, qs2); FMA_F32X2(dp2, m2, dt, tt);                \
        MUL_F32X2_(dt, qx2, Xb.y); FMA_F32X2(dt, qy2, Yb.y, dt);              \
        FMA_F32X2(dt, qz2, Zb.y, dt);                                         \
        ADD_F32X2_(tt, Sb.y, qs2); FMA_F32X2(dp3, m2, dt, tt);                \
        unsigned u0, u1, u2, u3, u4, u5, u6, u7;                              \
        UNPACK2(u0, u1, dp0); UNPACK2(u2, u3, dp1);                           \
        UNPACK2(u4, u5, dp2); UNPACK2(u6, u7, dp3);                           \
        PUSHB(__uint_as_float(u0), j0 + 0);                                   \
        PUSHB(__uint_as_float(u1), j0 + 1);                                   \
        PUSHB(__uint_as_float(u2), j0 + 2);                                   \
        PUSHB(__uint_as_float(u3), j0 + 3);                                   \
        PUSHB(__uint_as_float(u4), j0 + 4);                                   \
        PUSHB(__uint_as_float(u5), j0 + 5);                                   \
        PUSHB(__uint_as_float(u6), j0 + 6);                                   \
        PUSHB(__uint_as_float(u7), j0 + 7);                                   \
    }

// ---------------------------------------------------------------- build ----
__global__ __launch_bounds__(TPB, 1)
void knn_build_kernel(const float* __restrict__ pos)
{
    __shared__ int cnt[NB + 1];
    const int g = blockIdx.x, tid = threadIdx.x, base = g * NPER;
    const float* gp = pos + (size_t)base * 3;

    if (tid <= NB) cnt[tid] = 0;
    __syncthreads();

    for (int p = tid; p < NPER; p += TPB)
        atomicAdd(&cnt[zbin(gp[3 * p + 2])], 1);
    __syncthreads();

    if (tid == 0) {
        int run = 0;
        for (int i = 0; i < NB; ++i) { const int v = cnt[i]; cnt[i] = run; run += v; }
        cnt[NB] = run;
    }
    __syncthreads();

    // scatter into z-sorted SoA; norm op order matches the query dot chain
    // so the self-distance evaluates to exactly +0.
    for (int p = tid; p < NPER; p += TPB) {
        const float x = gp[3 * p], y = gp[3 * p + 1], z = gp[3 * p + 2];
        const int slot = atomicAdd(&cnt[zbin(z)], 1);
        g_sx[g][slot] = x; g_sy[g][slot] = y; g_sz[g][slot] = z;
        g_ss[g][slot] = fmaf(z, z, fmaf(y, y, x * x));
        g_sidx[g][slot] = (unsigned short)p;
    }
}

// ---------------------------------------------------------------- query ----
__global__ __launch_bounds__(TPB, 2)
void knn_query_kernel(float* __restrict__ out, int total_n)
{
    extern __shared__ char smraw[];
    float* sx = (float*)(smraw + SM_SX);
    float* sy = (float*)(smraw + SM_SY);
    float* sz = (float*)(smraw + SM_SZ);
    float* ss = (float*)(smraw + SM_SS);
    unsigned short*     sidx  = (unsigned short*)(smraw + SM_SIDX);
    unsigned long long* pend  = (unsigned long long*)(smraw + SM_PEND);
    float*              zbmin = (float*)(smraw + SM_ZBMIN);
    float*              zbmax = (float*)(smraw + SM_ZBMAX);

    const int graph = blockIdx.x / CPG;
    const int base  = graph * NPER;
    const int tid   = threadIdx.x;

    for (int p = tid; p < NPER; p += TPB) {
        sx[p] = g_sx[graph][p];
        sy[p] = g_sy[graph][p];
        sz[p] = g_sz[graph][p];
        ss[p] = g_ss[graph][p];
        sidx[p] = g_sidx[graph][p];
    }
    __syncthreads();

    // Per-block conservative z-bounds from bin edges (clamp-safe: bin 0 has
    // no lower bound, bin NB-1 no upper bound). zbin(sz[j]) is non-decreasing
    // in j (bin-major sort), so block bins = [zbin(sz[8b]), zbin(sz[8b+7])].
    for (int b = tid; b < NBLK; b += TPB) {
        const int b1 = zbin(sz[b * 8]);
        const int b2 = zbin(sz[b * 8 + 7]);
        zbmin[b] = (b1 == 0)      ? -CUDART_INF_F : ZLO + (float)b1 * HB;
        zbmax[b] = (b2 == NB - 1) ?  CUDART_INF_F : ZLO + (float)(b2 + 1) * HB;
    }
    __syncthreads();

    const int   s  = (blockIdx.x % CPG) * TPB + tid;   // sorted slot = query
    const float qx = sx[s], qy = sy[s], qz = sz[s], qs = ss[s];
    const int   qi = (int)sidx[s];

    unsigned long long bk[KP1];
#pragma unroll
    for (int m = 0; m < KP1; ++m) bk[m] = INIT_KEY;
    float worstf = CUDART_INF_F;

    unsigned long long qx2, qy2, qz2, qs2, m2;
    {
        const unsigned xb = __float_as_uint(qx), yb = __float_as_uint(qy);
        const unsigned zb = __float_as_uint(qz), sb = __float_as_uint(qs);
        const unsigned nb = __float_as_uint(-2.0f);
        PACK2(qx2, xb, xb); PACK2(qy2, yb, yb); PACK2(qz2, zb, zb);
        PACK2(qs2, sb, sb); PACK2(m2, nb, nb);
    }

    unsigned offb = 0;
    const unsigned pbase = (unsigned)__cvta_generic_to_shared(pend + tid);

    // ---- seed: the warp's own 64-slot neighborhood (z-nearest; includes
    // self). Warp-uniform block range -> uniform control flow.
    const int W0 = (blockIdx.x % CPG) * TPB + (tid & ~31);
    int seedB = (W0 - 16) / 8;
    seedB = max(0, min(NBLK - 8, seedB));

#pragma unroll 1
    for (int b = seedB; b < seedB + 8; ++b) {
        SCAN_BLOCK(b);
        if (__any_sync(0xFFFFFFFFu, offb >= FLUSH_B)) DRAIN();
    }
    DRAIN();                     // list now full (64 >= 17), worstf finite

    float zlo_w, zhi_w;
    REDUCE_BOUNDS();

    // ---- sweep all other blocks with warp-uniform z-skip ----
#pragma unroll 1
    for (int b = 0; b < NBLK; ++b) {
        if (b >= seedB && b < seedB + 8) continue;        // no duplicates
        if (zbmin[b] > zhi_w) continue;                   // block all too high
        if (zbmax[b] < zlo_w) continue;                   // block all too low
        SCAN_BLOCK(b);
        if (__any_sync(0xFFFFFFFFu, offb >= FLUSH_B)) {
            DRAIN();
            REDUCE_BOUNDS();                              // window shrinks
        }
    }
    DRAIN();

    // Emit: drop the single self entry (orig idx == qi, d == +0), keep K.
    const int    gq = base + qi;
    const size_t Nk = (size_t)total_n * K;
    int w = 0;
#pragma unroll
    for (int m = 0; m < KP1; ++m) {
        const int      idx = (int)(unsigned)bk[m];
        const unsigned hi  = (unsigned)(bk[m] >> 32);
        const unsigned du  = (hi & 0x80000000u) ? (hi ^ 0x80000000u) : ~hi;
        if (idx != qi && w < K) {
            const size_t e = (size_t)gq * K + w;
            out[e]          = (float)(idx + base);
            out[Nk + e]     = (float)gq;
            out[2 * Nk + e] = __uint_as_float(du);
            ++w;
        }
    }
}

extern "C" void kernel_launch(void* const* d_in, const int* in_sizes, int n_in,
                              void* d_out, int out_size)
{
    const float* pos = (const float*)d_in[0];
    const int total_n = in_sizes[0] / 3;
    const int ngraphs = total_n / NPER;

    knn_build_kernel<<<ngraphs, TPB>>>(pos);

    cudaFuncSetAttribute(knn_query_kernel,
                         cudaFuncAttributeMaxDynamicSharedMemorySize, SM_TOTAL);
    knn_query_kernel<<<ngraphs * CPG, TPB, SM_TOTAL>>>((float*)d_out, total_n);
}

// round 15
// speedup vs baseline: 1.9386x; 1.9386x over previous
#include <cuda_runtime.h>
#include <math_constants.h>

// kNN graph, PyG knn_graph(loop=False): B=16 graphs x n=4096 pts, D=3, k=16.
// R6 dense 8-wide engine with: index-only FIFO (u32), 16-wide flush voting.
// Output (float32 flat): [nbr_global | centers | topk_d2], each total_n*K,
// ordering (b*n+i)*K + m (matches reference reshape(-1)).

#define K        16
#define KP1      17            // keep k+1; self entry removed at output
#define NPER     4096
#define TPB      256
#define CPG      (NPER / TPB)  // 16 CTAs per graph
#define PB       20            // u32 FIFO slots: cnt<=4 entering body, +16 = 20
#define SLOT_B   (TPB * 4u)    // 1024 B between a thread's slots
#define FLUSH_B  (5u * SLOT_B) // flush when cnt >= 5

// smem byte offsets
#define SM_SX    0
#define SM_SY    16384
#define SM_SZ    32768
#define SM_SS    49152
#define SM_PEND  65536                  // u32[PB][256] = 20480
#define SM_TOTAL (65536 + 20480)        // 86016 -> 2 CTAs/SM

#define FMA_F32X2(out, a, b, c) \
    asm("fma.rn.f32x2 %0, %1, %2, %3;" : "=l"(out) : "l"(a), "l"(b), "l"(c))
#define MUL_F32X2_(out, a, b) \
    asm("mul.rn.f32x2 %0, %1, %2;" : "=l"(out) : "l"(a), "l"(b))
#define ADD_F32X2_(out, a, b) \
    asm("add.rn.f32x2 %0, %1, %2;" : "=l"(out) : "l"(a), "l"(b))
#define PACK2(out, lo, hi) \
    asm("mov.b64 %0, {%1, %2};" : "=l"(out) : "r"(lo), "r"(hi))
#define UNPACK2(lo, hi, in) \
    asm("mov.b64 {%0, %1}, %2;" : "=r"(lo), "=r"(hi) : "l"(in))

// Branchless predicated push, index only: setp.le guards the u32 store and
// (via selp) yields the {0, SLOT_B} offset increment. No BSSY/BSYNC.
#define PUSH32(dv, jv)                                                        \
    do {                                                                      \
        unsigned inc_;                                                        \
        asm volatile(                                                         \
            "{\n\t.reg .pred p;\n\t"                                          \
            "setp.le.f32 p, %1, %2;\n\t"                                      \
            "selp.u32 %0, %3, 0, p;\n\t"                                      \
            "@p st.shared.b32 [%4], %5;\n\t}"                                 \
            : "=r"(inc_)                                                      \
            : "f"(dv), "f"(worst), "n"(SLOT_B),                               \
              "r"(pbase + offb), "r"((unsigned)(jv))                          \
            : "memory");                                                      \
        offb += inc_;                                                         \
    } while (0)

// Drain this lane's FIFO (indices only; distance recomputed with the exact
// same fma sequence -> identical bits). Per-lane divergent guard + strict '<'
// sorted-insert chain: FIFO arrival order is ascending j, so equal distances
// keep the earlier/lower index — jax.lax.top_k semantics (R6-validated).
#define DRAIN()                                                               \
    {                                                                         \
        const int cnt_ = (int)(offb >> 10);                                   \
        offb = 0;                                                             \
        const unsigned* myp_ = pend + tid;                                    \
        _Pragma("unroll 1")                                                   \
        for (int p_ = 0; p_ < cnt_; ++p_) {                                   \
            const int jc_ = (int)myp_[(size_t)p_ * TPB];                      \
            const float dot_ =                                                \
                fmaf(qz, sz[jc_], fmaf(qy, sy[jc_], qx * sx[jc_]));           \
            float dc_ = fmaf(-2.f, dot_, qs + ss[jc_]);                       \
            int   ic_ = jc_;                                                  \
            if (dc_ < worst) {                                                \
                _Pragma("unroll")                                             \
                for (int m_ = 0; m_ < KP1; ++m_) {                            \
                    const bool  sw_ = dc_ < bd[m_];                           \
                    const float fo_ = sw_ ? bd[m_] : dc_;                     \
                    const int   io_ = sw_ ? bi[m_] : ic_;                     \
                    bd[m_] = sw_ ? dc_ : bd[m_];                              \
                    bi[m_] = sw_ ? ic_ : bi[m_];                              \
                    dc_ = fo_; ic_ = io_;                                     \
                }                                                             \
                worst = bd[KP1 - 1];                                          \
            }                                                                 \
        }                                                                     \
    }

// 8 candidates: LDS.128 broadcasts, f32x2 distance (exact reference op
// order/rounding), 8 branchless pushes. NOTE: macro-local index is jb_
// (NOT j0) — naming it j0 and invoking BLOCK8(j0+8) would self-shadow and
// read an uninitialized variable (the R14 crash).
#define BLOCK8(j0_)                                                           \
    {                                                                         \
        const int jb_ = (j0_);                                                \
        const ulonglong2 Xa = *(const ulonglong2*)(sx + jb_);                 \
        const ulonglong2 Ya = *(const ulonglong2*)(sy + jb_);                 \
        const ulonglong2 Za = *(const ulonglong2*)(sz + jb_);                 \
        const ulonglong2 Sa = *(const ulonglong2*)(ss + jb_);                 \
        const ulonglong2 Xb = *(const ulonglong2*)(sx + jb_ + 4);             \
        const ulonglong2 Yb = *(const ulonglong2*)(sy + jb_ + 4);             \
        const ulonglong2 Zb = *(const ulonglong2*)(sz + jb_ + 4);             \
        const ulonglong2 Sb = *(const ulonglong2*)(ss + jb_ + 4);             \
        unsigned long long dt, tt, dp0, dp1, dp2, dp3;                        \
        MUL_F32X2_(dt, qx2, Xa.x); FMA_F32X2(dt, qy2, Ya.x, dt);              \
        FMA_F32X2(dt, qz2, Za.x, dt);                                         \
        ADD_F32X2_(tt, Sa.x, qs2); FMA_F32X2(dp0, m2, dt, tt);                \
        MUL_F32X2_(dt, qx2, Xa.y); FMA_F32X2(dt, qy2, Ya.y, dt);              \
        FMA_F32X2(dt, qz2, Za.y, dt);                                         \
        ADD_F32X2_(tt, Sa.y, qs2); FMA_F32X2(dp1, m2, dt, tt);                \
        MUL_F32X2_(dt, qx2, Xb.x); FMA_F32X2(dt, qy2, Yb.x, dt);              \
        FMA_F32X2(dt, qz2, Zb.x, dt);                                         \
        ADD_F32X2_(tt, Sb.x, qs2); FMA_F32X2(dp2, m2, dt, tt);                \
        MUL_F32X2_(dt, qx2, Xb.y); FMA_F32X2(dt, qy2, Yb.y, dt);              \
        FMA_F32X2(dt, qz2, Zb.y, dt);                                         \
        ADD_F32X2_(tt, Sb.y, qs2); FMA_F32X2(dp3, m2, dt, tt);                \
        unsigned u0, u1, u2, u3, u4, u5, u6, u7;                              \
        UNPACK2(u0, u1, dp0); UNPACK2(u2, u3, dp1);                           \
        UNPACK2(u4, u5, dp2); UNPACK2(u6, u7, dp3);                           \
        PUSH32(__uint_as_float(u0), jb_ + 0);                                 \
        PUSH32(__uint_as_float(u1), jb_ + 1);                                 \
        PUSH32(__uint_as_float(u2), jb_ + 2);                                 \
        PUSH32(__uint_as_float(u3), jb_ + 3);                                 \
        PUSH32(__uint_as_float(u4), jb_ + 4);                                 \
        PUSH32(__uint_as_float(u5), jb_ + 5);                                 \
        PUSH32(__uint_as_float(u6), jb_ + 6);                                 \
        PUSH32(__uint_as_float(u7), jb_ + 7);                                 \
    }

__global__ __launch_bounds__(TPB, 2)
void knn_topk_kernel(const float* __restrict__ pos,
                     float* __restrict__ out,
                     int total_n)
{
    extern __shared__ char smraw[];
    float*    sx   = (float*)(smraw + SM_SX);
    float*    sy   = (float*)(smraw + SM_SY);
    float*    sz   = (float*)(smraw + SM_SZ);
    float*    ss   = (float*)(smraw + SM_SS);
    unsigned* pend = (unsigned*)(smraw + SM_PEND);

    const int graph = blockIdx.x / CPG;
    const int base  = graph * NPER;
    const float* gp = pos + (size_t)base * 3;

    // Stage graph points (SoA) + squared norms. ss uses the SAME op order as
    // the dot chain so the self-distance is exactly +0.
    for (int p = threadIdx.x; p < NPER; p += TPB) {
        float x = gp[3 * p + 0];
        float y = gp[3 * p + 1];
        float z = gp[3 * p + 2];
        sx[p] = x; sy[p] = y; sz[p] = z;
        ss[p] = fmaf(z, z, fmaf(y, y, x * x));
    }
    __syncthreads();

    const int   tid = threadIdx.x;
    const int   q   = (blockIdx.x % CPG) * TPB + tid;
    const float qx = sx[q], qy = sy[q], qz = sz[q], qs = ss[q];

    unsigned long long qx2, qy2, qz2, qs2, m2;
    {
        const unsigned xb = __float_as_uint(qx), yb = __float_as_uint(qy);
        const unsigned zb = __float_as_uint(qz), sb = __float_as_uint(qs);
        const unsigned nb = __float_as_uint(-2.0f);
        PACK2(qx2, xb, xb); PACK2(qy2, yb, yb); PACK2(qz2, zb, zb);
        PACK2(qs2, sb, sb); PACK2(m2, nb, nb);
    }

    // Sorted K+1 list (ascending; FIFO order + strict '<' chain => ties keep
    // the earlier/lower index). Self kept, removed at output.
    float bd[KP1];
    int   bi[KP1];
#pragma unroll
    for (int m = 0; m < KP1; ++m) { bd[m] = CUDART_INF_F; bi[m] = -1; }
    float worst = CUDART_INF_F;

    unsigned offb = 0;   // FIFO fill in bytes (slot stride SLOT_B)
    const unsigned pbase = (unsigned)__cvta_generic_to_shared(pend + tid);

#pragma unroll 1
    for (int j0 = 0; j0 < NPER; j0 += 16) {
        BLOCK8(j0);
        BLOCK8(j0 + 8);
        // One warp-uniform flush vote per 16 candidates.
        if (__any_sync(0xFFFFFFFFu, offb >= FLUSH_B)) DRAIN();
    }

    DRAIN();

    // Emit: drop the single self entry (idx == q, d == +0), keep first K.
    const int    gq = base + q;
    const size_t Nk = (size_t)total_n * K;
    int w = 0;
#pragma unroll
    for (int m = 0; m < KP1; ++m) {
        if (bi[m] != q && w < K) {
            const size_t e = (size_t)gq * K + w;
            out[e]          = (float)(bi[m] + base);
            out[Nk + e]     = (float)gq;
            out[2 * Nk + e] = bd[m];
            ++w;
        }
    }
}

extern "C" void kernel_launch(void* const* d_in, const int* in_sizes, int n_in,
                              void* d_out, int out_size)
{
    const float* pos = (const float*)d_in[0];
    const int total_n = in_sizes[0] / 3;
    const int ngraphs = total_n / NPER;

    cudaFuncSetAttribute(knn_topk_kernel,
                         cudaFuncAttributeMaxDynamicSharedMemorySize, SM_TOTAL);
    knn_topk_kernel<<<ngraphs * CPG, TPB, SM_TOTAL>>>(pos, (float*)d_out, total_n);
}